// round 3
// baseline (speedup 1.0000x reference)
#include <cuda_runtime.h>

// Problem constants (fixed by setup_inputs: B=32, NT=32, NP=8192)
#define SLABS 1024            // B*NT
#define SLAB_F4 6144          // 8192 points * 3 floats / 4
#define THREADS 256
#define WARPS 8               // per block
#define WTILE_F4 96           // one warp-tile: 32 lanes * 3 float4 = 128 points... (96 f4 = 128 pts)
#define TILES_PER_WARP 4
#define GRID 2048             // 2048*8 warps * 4 tiles * 96 f4 = 6.29M f4 = full tensor
// warp-tiles per slab = 6144/96 = 64; a warp's 4 consecutive tiles stay in one slab.

__global__ __launch_bounds__(THREADS) void fused_xform_kernel(
    const float4* __restrict__ X, const float* __restrict__ dof,
    float4* __restrict__ out)
{
    const int w   = threadIdx.x >> 5;       // warp in block
    const int l   = threadIdx.x & 31;       // lane
    const int gw  = blockIdx.x * WARPS + w; // global warp id
    const int slab = gw >> 4;               // gw*4/64: constant for all 4 tiles

    // ---- per-slab SE(3) exp (once per warp, redundant across lanes) ----
    const float* d = dof + slab * 6;
    float vx = d[0], vy = d[1], vz = d[2];
    float wx = d[3], wy = d[4], wz = d[5];
    float t2 = wx*wx + wy*wy + wz*wz;
    float th = sqrtf(t2);
    float A, B, C;
    if (th < 1e-4f) {
        A = 1.0f - t2 * (1.0f/6.0f);
        B = 0.5f - t2 * (1.0f/24.0f);
        C = (1.0f/6.0f) - t2 * (1.0f/120.0f);
    } else {
        float s, c;
        sincosf(th, &s, &c);
        A = s / th;
        B = (1.0f - c) / t2;
        C = (th - s) / (t2 * th);
    }
    // K^2 = w w^T - t2*I
    float r00 = 1.0f + B*(wx*wx - t2);
    float r01 = -A*wz + B*wx*wy;
    float r02 =  A*wy + B*wx*wz;
    float r10 =  A*wz + B*wx*wy;
    float r11 = 1.0f + B*(wy*wy - t2);
    float r12 = -A*wx + B*wy*wz;
    float r20 = -A*wy + B*wx*wz;
    float r21 =  A*wx + B*wy*wz;
    float r22 = 1.0f + B*(wz*wz - t2);

    float v00 = 1.0f + C*(wx*wx - t2);
    float v01 = -B*wz + C*wx*wy;
    float v02 =  B*wy + C*wx*wz;
    float v10 =  B*wz + C*wx*wy;
    float v11 = 1.0f + C*(wy*wy - t2);
    float v12 = -B*wx + C*wy*wz;
    float v20 = -B*wy + C*wx*wz;
    float v21 =  B*wx + C*wy*wz;
    float v22 = 1.0f + C*(wz*wz - t2);

    float tx = v00*vx + v01*vy + v02*vz;
    float ty = v10*vx + v11*vy + v12*vz;
    float tz = v20*vx + v21*vy + v22*vz;

    // ---- warp-private staging (no block barriers anywhere) ----
    __shared__ float4 s_in [WARPS][WTILE_F4];
    __shared__ float4 s_out[WARPS][WTILE_F4];

    long base = (long)(gw * TILES_PER_WARP) * WTILE_F4;

    // prefetch tile 0 into registers
    float4 p0 = X[base +  0 + l];
    float4 p1 = X[base + 32 + l];
    float4 p2 = X[base + 64 + l];

    #pragma unroll
    for (int t = 0; t < TILES_PER_WARP; t++) {
        const long tb = base + (long)t * WTILE_F4;

        // stage registers -> smem
        s_in[w][ 0 + l] = p0;
        s_in[w][32 + l] = p1;
        s_in[w][64 + l] = p2;
        __syncwarp();

        // prefetch next tile (independent; overlaps compute below)
        if (t + 1 < TILES_PER_WARP) {
            p0 = X[tb + WTILE_F4 +  0 + l];
            p1 = X[tb + WTILE_F4 + 32 + l];
            p2 = X[tb + WTILE_F4 + 64 + l];
        }

        // per-point work from SMEM (LDS.128 word-stride 12: conflict-free)
        float4 a = s_in[w][3 * l + 0];
        float4 b = s_in[w][3 * l + 1];
        float4 c = s_in[w][3 * l + 2];

        // 4 points packed across 3 float4s:
        // pA=(a.x,a.y,a.z) pB=(a.w,b.x,b.y) pC=(b.z,b.w,c.x) pD=(c.y,c.z,c.w)
        float ox0 = fmaf(r00, a.x, fmaf(r01, a.y, fmaf(r02, a.z, tx)));
        float oy0 = fmaf(r10, a.x, fmaf(r11, a.y, fmaf(r12, a.z, ty)));
        float oz0 = fmaf(r20, a.x, fmaf(r21, a.y, fmaf(r22, a.z, tz)));

        float ox1 = fmaf(r00, a.w, fmaf(r01, b.x, fmaf(r02, b.y, tx)));
        float oy1 = fmaf(r10, a.w, fmaf(r11, b.x, fmaf(r12, b.y, ty)));
        float oz1 = fmaf(r20, a.w, fmaf(r21, b.x, fmaf(r22, b.y, tz)));

        float ox2 = fmaf(r00, b.z, fmaf(r01, b.w, fmaf(r02, c.x, tx)));
        float oy2 = fmaf(r10, b.z, fmaf(r11, b.w, fmaf(r12, c.x, ty)));
        float oz2 = fmaf(r20, b.z, fmaf(r21, b.w, fmaf(r22, c.x, tz)));

        float ox3 = fmaf(r00, c.y, fmaf(r01, c.z, fmaf(r02, c.w, tx)));
        float oy3 = fmaf(r10, c.y, fmaf(r11, c.z, fmaf(r12, c.w, ty)));
        float oz3 = fmaf(r20, c.y, fmaf(r21, c.z, fmaf(r22, c.w, tz)));

        s_out[w][3 * l + 0] = make_float4(ox0, oy0, oz0, ox1);
        s_out[w][3 * l + 1] = make_float4(oy1, oz1, ox2, oy2);
        s_out[w][3 * l + 2] = make_float4(oz2, ox3, oy3, oz3);
        __syncwarp();

        // stage-out: unit-stride, streaming hint (keep input L2-resident)
        __stcs(&out[tb +  0 + l], s_out[w][ 0 + l]);
        __stcs(&out[tb + 32 + l], s_out[w][32 + l]);
        __stcs(&out[tb + 64 + l], s_out[w][64 + l]);
        __syncwarp();   // protect s_in/s_out reuse next iteration
    }
}

extern "C" void kernel_launch(void* const* d_in, const int* in_sizes, int n_in,
                              void* d_out, int out_size) {
    const float4* X   = (const float4*)d_in[0];   // X_v: 32*32*8192*3 f32
    const float*  dof = (const float*)d_in[1];    // dof: 32*32*6 f32
    float4* out = (float4*)d_out;

    fused_xform_kernel<<<GRID, THREADS>>>(X, dof, out);
}

// round 4
// speedup vs baseline: 1.0482x; 1.0482x over previous
#include <cuda_runtime.h>

// Problem constants (fixed by setup_inputs: B=32, NT=32, NP=8192)
// Total float4 count: 32*32*8192*3/4 = 6,291,456
#define THREADS 256
#define WARPS 8
#define WTILE_F4 96            // one warp-tile: 3 float4 per lane = 128 points
#define TILES_PER_WARP 4
#define GRID 2048              // 2048*8*4*96 = 6,291,456 f4 (exact cover)
#define SLAB_F4 6144           // per (b,t): 8192*3/4; warp's 4 tiles stay in one slab

#define FULL 0xFFFFFFFFu

__global__ __launch_bounds__(THREADS) void fused_xform_kernel(
    const float4* __restrict__ X, const float* __restrict__ dof,
    float4* __restrict__ out)
{
    const int w  = threadIdx.x >> 5;
    const int l  = threadIdx.x & 31;
    const int gw = blockIdx.x * WARPS + w;        // global warp id
    const int slab = gw >> 4;                     // 64 warp-tiles per slab / 4 per warp

    // ---- per-slab SE(3) exp (redundant across lanes of the warp) ----
    const float* d = dof + slab * 6;
    float vx = d[0], vy = d[1], vz = d[2];
    float wx = d[3], wy = d[4], wz = d[5];
    float t2 = wx*wx + wy*wy + wz*wz;
    float th = sqrtf(t2);
    float A, B, C;
    if (th < 1e-4f) {
        A = 1.0f - t2 * (1.0f/6.0f);
        B = 0.5f - t2 * (1.0f/24.0f);
        C = (1.0f/6.0f) - t2 * (1.0f/120.0f);
    } else {
        float s, c;
        sincosf(th, &s, &c);
        A = s / th;
        B = (1.0f - c) / t2;
        C = (th - s) / (t2 * th);
    }
    // K^2 = w w^T - t2*I
    const float r00 = 1.0f + B*(wx*wx - t2);
    const float r01 = -A*wz + B*wx*wy;
    const float r02 =  A*wy + B*wx*wz;
    const float r10 =  A*wz + B*wx*wy;
    const float r11 = 1.0f + B*(wy*wy - t2);
    const float r12 = -A*wx + B*wy*wz;
    const float r20 = -A*wy + B*wx*wz;
    const float r21 =  A*wx + B*wy*wz;
    const float r22 = 1.0f + B*(wz*wz - t2);

    const float v00 = 1.0f + C*(wx*wx - t2);
    const float v01 = -B*wz + C*wx*wy;
    const float v02 =  B*wy + C*wx*wz;
    const float v10 =  B*wz + C*wx*wy;
    const float v11 = 1.0f + C*(wy*wy - t2);
    const float v12 = -B*wx + C*wy*wz;
    const float v20 = -B*wy + C*wx*wz;
    const float v21 =  B*wx + C*wy*wz;
    const float v22 = 1.0f + C*(wz*wz - t2);

    const float tx = v00*vx + v01*vy + v02*vz;
    const float ty = v10*vx + v11*vy + v12*vz;
    const float tz = v20*vx + v21*vy + v22*vz;

    // phase of float4 index (32*j + l) is (2*j + l) mod 3
    const int lm = l % 3;
    const bool e0 = (l == 0), e31 = (l == 31);

    const long base = (long)gw * (TILES_PER_WARP * WTILE_F4);

    // prefetch tile 0
    float4 a0 = X[base +  0 + l];
    float4 a1 = X[base + 32 + l];
    float4 a2 = X[base + 64 + l];

    #pragma unroll
    for (int t = 0; t < TILES_PER_WARP; t++) {
        const long tb = base + (long)t * WTILE_F4;

        float4 b0, b1, b2;
        if (t + 1 < TILES_PER_WARP) {          // prefetch next tile (overlaps compute)
            b0 = X[tb + WTILE_F4 +  0 + l];
            b1 = X[tb + WTILE_F4 + 32 + l];
            b2 = X[tb + WTILE_F4 + 64 + l];
        }

        // cross-register boundary values (broadcasts)
        const float c1x = __shfl_sync(FULL, a1.x, 0);   // in[32].x  for j=0 lane31
        const float c1y = __shfl_sync(FULL, a1.y, 0);
        const float c2x = __shfl_sync(FULL, a2.x, 0);   // in[64].x  for j=1 lane31
        const float c2y = __shfl_sync(FULL, a2.y, 0);
        const float p0z = __shfl_sync(FULL, a0.z, 31);  // in[31].zw for j=1 lane0
        const float p0w = __shfl_sync(FULL, a0.w, 31);
        const float p1z = __shfl_sync(FULL, a1.z, 31);  // in[63].zw for j=2 lane0
        const float p1w = __shfl_sync(FULL, a1.w, 31);

        #pragma unroll
        for (int j = 0; j < 3; j++) {
            const float4 r = (j == 0) ? a0 : (j == 1) ? a1 : a2;

            // neighbors: prev = in[32j+l-1].zw, next = in[32j+l+1].xy
            float pz = __shfl_up_sync(FULL, r.z, 1);
            float pw = __shfl_up_sync(FULL, r.w, 1);
            float nx = __shfl_down_sync(FULL, r.x, 1);
            float ny = __shfl_down_sync(FULL, r.y, 1);
            if (j == 1 && e0)  { pz = p0z; pw = p0w; }
            if (j == 2 && e0)  { pz = p1z; pw = p1w; }
            if (j == 0 && e31) { nx = c1x; ny = c1y; }
            if (j == 1 && e31) { nx = c2x; ny = c2y; }
            // j==0,l==0: phase 0 -> prev unused; j==2,l==31: phase 2 -> next unused

            const int ph = (lm + 2 * j) % 3;   // j compile-time, folds to lm/(lm+2)%3/(lm+1)%3
            const bool is0 = (ph == 0), is1 = (ph == 1);

            // first point F and second point S covered by this output float4
            const float Fx = is0 ? r.x : (is1 ? pw  : pz);
            const float Fy = is0 ? r.y : (is1 ? r.x : pw);
            const float Fz = is0 ? r.z : (is1 ? r.y : r.x);
            const float Sx = is0 ? r.w : (is1 ? r.z : r.y);
            const float Sy = is0 ? nx  : (is1 ? r.w : r.z);
            const float Sz = is0 ? ny  : (is1 ? nx  : r.w);

            const float qFx = fmaf(r00, Fx, fmaf(r01, Fy, fmaf(r02, Fz, tx)));
            const float qFy = fmaf(r10, Fx, fmaf(r11, Fy, fmaf(r12, Fz, ty)));
            const float qFz = fmaf(r20, Fx, fmaf(r21, Fy, fmaf(r22, Fz, tz)));
            const float qSx = fmaf(r00, Sx, fmaf(r01, Sy, fmaf(r02, Sz, tx)));
            const float qSy = fmaf(r10, Sx, fmaf(r11, Sy, fmaf(r12, Sz, ty)));
            const float qSz = fmaf(r20, Sx, fmaf(r21, Sy, fmaf(r22, Sz, tz)));

            // output = window of [qF.x,qF.y,qF.z,qS.x,qS.y,qS.z] starting at phase
            float4 o;
            o.x = is0 ? qFx : (is1 ? qFy : qFz);
            o.y = is0 ? qFy : (is1 ? qFz : qSx);
            o.z = is0 ? qFz : (is1 ? qSx : qSy);
            o.w = is0 ? qSx : (is1 ? qSy : qSz);

            __stcs(&out[tb + 32 * j + l], o);
        }

        a0 = b0; a1 = b1; a2 = b2;
    }
}

extern "C" void kernel_launch(void* const* d_in, const int* in_sizes, int n_in,
                              void* d_out, int out_size) {
    const float4* X   = (const float4*)d_in[0];   // X_v: 32*32*8192*3 f32
    const float*  dof = (const float*)d_in[1];    // dof: 32*32*6 f32
    float4* out = (float4*)d_out;

    fused_xform_kernel<<<GRID, THREADS>>>(X, dof, out);
}

// round 6
// speedup vs baseline: 1.0564x; 1.0078x over previous
#include <cuda_runtime.h>

// Problem constants (fixed by setup_inputs: B=32, NT=32, NP=8192)
// Total float4 count: 32*32*8192*3/4 = 6,291,456
#define THREADS 256
#define WARPS 8
#define WTILE_F4 96            // one warp-tile: 3 float4 per lane = 128 points
#define TILES_PER_WARP 4
#define GRID 2048              // 2048*8*4*96 = 6,291,456 f4 (exact cover)

#define FULL 0xFFFFFFFFu

// L2 eviction policies via createpolicy + cache_hint (the only encoding ptxas
// accepts for 128-bit accesses on this toolchain).
__device__ __forceinline__ unsigned long long mk_policy_evict_last() {
    unsigned long long p;
    asm("createpolicy.fractional.L2::evict_last.b64 %0, 1.0;" : "=l"(p));
    return p;
}
__device__ __forceinline__ unsigned long long mk_policy_evict_first() {
    unsigned long long p;
    asm("createpolicy.fractional.L2::evict_first.b64 %0, 1.0;" : "=l"(p));
    return p;
}
__device__ __forceinline__ float4 ldg_hint(const float4* p, unsigned long long pol) {
    float4 v;
    asm("ld.global.nc.L2::cache_hint.v4.f32 {%0,%1,%2,%3}, [%4], %5;"
        : "=f"(v.x), "=f"(v.y), "=f"(v.z), "=f"(v.w) : "l"(p), "l"(pol));
    return v;
}
__device__ __forceinline__ void stg_hint(float4* p, float4 v, unsigned long long pol) {
    asm volatile("st.global.L2::cache_hint.v4.f32 [%0], {%1,%2,%3,%4}, %5;"
        :: "l"(p), "f"(v.x), "f"(v.y), "f"(v.z), "f"(v.w), "l"(pol) : "memory");
}

__global__ __launch_bounds__(THREADS) void fused_xform_kernel(
    const float4* __restrict__ X, const float* __restrict__ dof,
    float4* __restrict__ out)
{
    const int w  = threadIdx.x >> 5;
    const int l  = threadIdx.x & 31;
    const int gw = blockIdx.x * WARPS + w;        // global warp id
    const int slab = gw >> 4;                     // 64 warp-tiles per slab / 4 per warp

    const unsigned long long POL_L = mk_policy_evict_last();
    const unsigned long long POL_F = mk_policy_evict_first();

    // ---- per-slab SE(3) exp (redundant across lanes of the warp) ----
    const float* d = dof + slab * 6;
    float vx = d[0], vy = d[1], vz = d[2];
    float wx = d[3], wy = d[4], wz = d[5];
    float t2 = wx*wx + wy*wy + wz*wz;
    float th = sqrtf(t2);
    float A, B, C;
    if (th < 1e-4f) {
        A = 1.0f - t2 * (1.0f/6.0f);
        B = 0.5f - t2 * (1.0f/24.0f);
        C = (1.0f/6.0f) - t2 * (1.0f/120.0f);
    } else {
        float s, c;
        sincosf(th, &s, &c);
        A = s / th;
        B = (1.0f - c) / t2;
        C = (th - s) / (t2 * th);
    }
    // K^2 = w w^T - t2*I
    const float r00 = 1.0f + B*(wx*wx - t2);
    const float r01 = -A*wz + B*wx*wy;
    const float r02 =  A*wy + B*wx*wz;
    const float r10 =  A*wz + B*wx*wy;
    const float r11 = 1.0f + B*(wy*wy - t2);
    const float r12 = -A*wx + B*wy*wz;
    const float r20 = -A*wy + B*wx*wz;
    const float r21 =  A*wx + B*wy*wz;
    const float r22 = 1.0f + B*(wz*wz - t2);

    const float v00 = 1.0f + C*(wx*wx - t2);
    const float v01 = -B*wz + C*wx*wy;
    const float v02 =  B*wy + C*wx*wz;
    const float v10 =  B*wz + C*wx*wy;
    const float v11 = 1.0f + C*(wy*wy - t2);
    const float v12 = -B*wx + C*wy*wz;
    const float v20 = -B*wy + C*wx*wz;
    const float v21 =  B*wx + C*wy*wz;
    const float v22 = 1.0f + C*(wz*wz - t2);

    const float tx = v00*vx + v01*vy + v02*vz;
    const float ty = v10*vx + v11*vy + v12*vz;
    const float tz = v20*vx + v21*vy + v22*vz;

    // phase of float4 index (32*j + l) is (2*j + l) mod 3
    const int lm = l % 3;
    const bool e0 = (l == 0), e31 = (l == 31);

    const long base = (long)gw * (TILES_PER_WARP * WTILE_F4);

    // prefetch tile 0
    float4 a0 = ldg_hint(&X[base +  0 + l], POL_L);
    float4 a1 = ldg_hint(&X[base + 32 + l], POL_L);
    float4 a2 = ldg_hint(&X[base + 64 + l], POL_L);

    #pragma unroll
    for (int t = 0; t < TILES_PER_WARP; t++) {
        const long tb = base + (long)t * WTILE_F4;

        float4 b0, b1, b2;
        if (t + 1 < TILES_PER_WARP) {          // prefetch next tile (overlaps compute)
            b0 = ldg_hint(&X[tb + WTILE_F4 +  0 + l], POL_L);
            b1 = ldg_hint(&X[tb + WTILE_F4 + 32 + l], POL_L);
            b2 = ldg_hint(&X[tb + WTILE_F4 + 64 + l], POL_L);
        }

        // cross-register boundary values (broadcasts)
        const float c1x = __shfl_sync(FULL, a1.x, 0);   // in[32].x  for j=0 lane31
        const float c1y = __shfl_sync(FULL, a1.y, 0);
        const float c2x = __shfl_sync(FULL, a2.x, 0);   // in[64].x  for j=1 lane31
        const float c2y = __shfl_sync(FULL, a2.y, 0);
        const float p0z = __shfl_sync(FULL, a0.z, 31);  // in[31].zw for j=1 lane0
        const float p0w = __shfl_sync(FULL, a0.w, 31);
        const float p1z = __shfl_sync(FULL, a1.z, 31);  // in[63].zw for j=2 lane0
        const float p1w = __shfl_sync(FULL, a1.w, 31);

        #pragma unroll
        for (int j = 0; j < 3; j++) {
            const float4 r = (j == 0) ? a0 : (j == 1) ? a1 : a2;

            // neighbors: prev = in[32j+l-1].zw, next = in[32j+l+1].xy
            float pz = __shfl_up_sync(FULL, r.z, 1);
            float pw = __shfl_up_sync(FULL, r.w, 1);
            float nx = __shfl_down_sync(FULL, r.x, 1);
            float ny = __shfl_down_sync(FULL, r.y, 1);
            if (j == 1 && e0)  { pz = p0z; pw = p0w; }
            if (j == 2 && e0)  { pz = p1z; pw = p1w; }
            if (j == 0 && e31) { nx = c1x; ny = c1y; }
            if (j == 1 && e31) { nx = c2x; ny = c2y; }
            // j==0,l==0: phase 0 -> prev unused; j==2,l==31: phase 2 -> next unused

            const int ph = (lm + 2 * j) % 3;   // j compile-time
            const bool is0 = (ph == 0), is1 = (ph == 1);

            // first point F and second point S covered by this output float4
            const float Fx = is0 ? r.x : (is1 ? pw  : pz);
            const float Fy = is0 ? r.y : (is1 ? r.x : pw);
            const float Fz = is0 ? r.z : (is1 ? r.y : r.x);
            const float Sx = is0 ? r.w : (is1 ? r.z : r.y);
            const float Sy = is0 ? nx  : (is1 ? r.w : r.z);
            const float Sz = is0 ? ny  : (is1 ? nx  : r.w);

            const float qFx = fmaf(r00, Fx, fmaf(r01, Fy, fmaf(r02, Fz, tx)));
            const float qFy = fmaf(r10, Fx, fmaf(r11, Fy, fmaf(r12, Fz, ty)));
            const float qFz = fmaf(r20, Fx, fmaf(r21, Fy, fmaf(r22, Fz, tz)));
            const float qSx = fmaf(r00, Sx, fmaf(r01, Sy, fmaf(r02, Sz, tx)));
            const float qSy = fmaf(r10, Sx, fmaf(r11, Sy, fmaf(r12, Sz, ty)));
            const float qSz = fmaf(r20, Sx, fmaf(r21, Sy, fmaf(r22, Sz, tz)));

            // output = window of [qF.x,qF.y,qF.z,qS.x,qS.y,qS.z] starting at phase
            float4 o;
            o.x = is0 ? qFx : (is1 ? qFy : qFz);
            o.y = is0 ? qFy : (is1 ? qFz : qSx);
            o.z = is0 ? qFz : (is1 ? qSx : qSy);
            o.w = is0 ? qSx : (is1 ? qSy : qSz);

            stg_hint(&out[tb + 32 * j + l], o, POL_F);
        }

        a0 = b0; a1 = b1; a2 = b2;
    }
}

extern "C" void kernel_launch(void* const* d_in, const int* in_sizes, int n_in,
                              void* d_out, int out_size) {
    const float4* X   = (const float4*)d_in[0];   // X_v: 32*32*8192*3 f32
    const float*  dof = (const float*)d_in[1];    // dof: 32*32*6 f32
    float4* out = (float4*)d_out;

    fused_xform_kernel<<<GRID, THREADS>>>(X, dof, out);
}